// round 2
// baseline (speedup 1.0000x reference)
#include <cuda_runtime.h>

#define Dh 256

#define NMAX 50016
#define EMAX 400128
#define GMAX 512

// ---------------- scratch (device globals; allocation-free) ----------------
__device__ float g_S[(size_t)NMAX * Dh];     // node scalar embedding s0, later updated s
__device__ float g_VN[(size_t)NMAX * 16];    // v_norm
__device__ float g_P[(size_t)NMAX * Dh];     // s0 @ Wm1[0:256]          (dst part)
__device__ float g_Q[(size_t)NMAX * Dh];     // s0 @ Wm1[256:512] + vn @ Wm1[512:528] (src part)
__device__ float g_AGG[(size_t)NMAX * Dh];   // scatter-sum of messages
__device__ int   g_CNT[NMAX];                // in-degree per node
__device__ int   g_GCNT[GMAX];               // nodes per graph
__device__ float g_Wed[17 * Dh];             // We[0:17] @ Wm1[528:784]
__device__ float g_bed[Dh];                  // bm1 + be @ Wm1[528:784]

// ---------------- packed f32x2 helpers ----------------
__device__ __forceinline__ void ffma2(unsigned long long &d, unsigned long long a, unsigned long long b) {
    asm("fma.rn.f32x2 %0, %1, %2, %0;" : "+l"(d) : "l"(a), "l"(b));
}
__device__ __forceinline__ unsigned long long packdup(float a) {
    unsigned long long r;
    asm("mov.b64 %0, {%1, %1};" : "=l"(r) : "f"(a));
    return r;
}
__device__ __forceinline__ float2 unpk(unsigned long long v) {
    float2 f;
    asm("mov.b64 {%0, %1}, %2;" : "=f"(f.x), "=f"(f.y) : "l"(v));
    return f;
}
__device__ __forceinline__ void atomAdd4(float* p, float4 v) {
    asm volatile("red.global.add.v4.f32 [%0], {%1,%2,%3,%4};"
                 :: "l"(p), "f"(v.x), "f"(v.y), "f"(v.z), "f"(v.w) : "memory");
}

// ---------------- GEMM building blocks (BM=128, BN=256, 512 threads) ----------------
// thread t: i = t>>5 -> rows 8i..8i+7 ; j = t&31 -> cols {4j..4j+3, 128+4j..128+4j+3}
__device__ __forceinline__ void stage_B(float* sB, const float* __restrict__ B, int k0, int K, int t) {
#pragma unroll
    for (int q = 0; q < 4; q++) {
        int idx = t + q * 512;            // 0..2047 -> 32x64 float4
        int kk = idx >> 6, c4 = idx & 63;
        float4 v = make_float4(0.f, 0.f, 0.f, 0.f);
        if (k0 + kk < K) v = *(const float4*)(B + (size_t)(k0 + kk) * Dh + c4 * 4);
        *(float4*)(sB + kk * Dh + c4 * 4) = v;
    }
}

__device__ __forceinline__ void mma_chunk(const float* aRow, int lda, const float* sB,
                                          int j, unsigned long long acc[8][4]) {
#pragma unroll
    for (int kk = 0; kk < 32; kk += 4) {
        float4 a4[8];
#pragma unroll
        for (int r = 0; r < 8; r++)
            a4[r] = *(const float4*)(aRow + r * lda + kk);
#pragma unroll
        for (int u = 0; u < 4; u++) {
            const float* brow = sB + (kk + u) * Dh + 4 * j;
            ulonglong2 b0 = *(const ulonglong2*)(brow);
            ulonglong2 b1 = *(const ulonglong2*)(brow + 128);
#pragma unroll
            for (int r = 0; r < 8; r++) {
                float av = (u == 0) ? a4[r].x : (u == 1) ? a4[r].y : (u == 2) ? a4[r].z : a4[r].w;
                unsigned long long pa = packdup(av);
                ffma2(acc[r][0], pa, b0.x);
                ffma2(acc[r][1], pa, b0.y);
                ffma2(acc[r][2], pa, b1.x);
                ffma2(acc[r][3], pa, b1.y);
            }
        }
    }
}

// Stage A = [g_S | g_VN | zeros] tile: 128 rows x 288 cols (272 real, 16 zero pad)
__device__ __forceinline__ void stage_A272(float* sA, int n0, int N, int t) {
    for (int idx = t; idx < 128 * 72; idx += 512) {
        int m = idx / 72, f4 = idx - m * 72;
        int n = n0 + m;
        float4 v = make_float4(0.f, 0.f, 0.f, 0.f);
        if (n < N) {
            if (f4 < 64)      v = *(const float4*)(g_S + (size_t)n * Dh + f4 * 4);
            else if (f4 < 68) v = *(const float4*)(g_VN + (size_t)n * 16 + (f4 - 64) * 4);
        }
        *(float4*)(sA + m * 288 + f4 * 4) = v;
    }
}

// ---------------- k_zero ----------------
__global__ void k_zero(float* out, int outN, int N, int G) {
    size_t stride = (size_t)gridDim.x * blockDim.x;
    size_t idx0 = (size_t)blockIdx.x * blockDim.x + threadIdx.x;
    for (size_t i = idx0; i < (size_t)N * Dh; i += stride) g_AGG[i] = 0.f;
    for (size_t i = idx0; i < (size_t)N; i += stride) g_CNT[i] = 0;
    for (size_t i = idx0; i < (size_t)G; i += stride) g_GCNT[i] = 0;
    for (size_t i = idx0; i < (size_t)outN; i += stride) out[i] = 0.f;
}

// ---------------- k_wed: fused edge weights ----------------
__global__ void k_wed(const float* __restrict__ We, const float* __restrict__ Wm1,
                      const float* __restrict__ bm1, const float* __restrict__ be) {
    __shared__ float w[256];
    int t = threadIdx.x, jb = blockIdx.x;
    w[t] = (jb < 17) ? We[(size_t)jb * 256 + t] : be[t];
    __syncthreads();
    float acc = (jb < 17) ? 0.f : bm1[t];
    const float* Wm = Wm1 + (size_t)528 * 256;
    for (int k = 0; k < 256; k++) acc = fmaf(w[k], Wm[(size_t)k * 256 + t], acc);
    if (jb < 17) g_Wed[jb * 256 + t] = acc;
    else         g_bed[t] = acc;
}

// ---------------- k_node: node embedding + vnorm ----------------
__global__ void k_node(const float* __restrict__ node_s, const float* __restrict__ node_v,
                       const float* __restrict__ Ws, const float* __restrict__ bs,
                       const float* __restrict__ Wv, const float* __restrict__ bv, int N) {
    __shared__ float sWs[23 * 256];
    __shared__ float sNS[32 * 23];
    __shared__ float sNV[32 * 12];
    __shared__ float sWv[64], sBv[16];
    int t = threadIdx.x;
    int n0 = blockIdx.x * 32;
    int nb = N - n0; if (nb > 32) nb = 32;
    for (int idx = t; idx < 23 * 256; idx += 256) sWs[idx] = Ws[idx];
    for (int idx = t; idx < nb * 23; idx += 256) sNS[idx] = node_s[(size_t)n0 * 23 + idx];
    for (int idx = t; idx < nb * 12; idx += 256) sNV[idx] = node_v[(size_t)n0 * 12 + idx];
    if (t < 64) sWv[t] = Wv[t];
    else if (t < 80) sBv[t - 64] = bv[t - 64];
    __syncthreads();
    float bsv = bs[t];
    for (int m = 0; m < nb; m++) {
        float acc = bsv;
#pragma unroll
        for (int jj = 0; jj < 23; jj++) acc = fmaf(sNS[m * 23 + jj], sWs[jj * 256 + t], acc);
        g_S[(size_t)(n0 + m) * Dh + t] = acc;
    }
    for (int idx = t; idx < nb * 16; idx += 256) {
        int m = idx >> 4, o = idx & 15;
        float ss = 0.f;
#pragma unroll
        for (int c = 0; c < 3; c++) {
            float v = sBv[o];
#pragma unroll
            for (int k = 0; k < 4; k++) v = fmaf(sNV[m * 12 + k * 3 + c], sWv[k * 16 + o], v);
            ss = fmaf(v, v, ss);
        }
        g_VN[(size_t)(n0 + m) * 16 + o] = sqrtf(ss);
    }
}

// ---------------- k_cnt: degree + graph counts ----------------
__global__ void k_cnt(const int* __restrict__ ei, const int* __restrict__ batch, int E, int N) {
    int idx = blockIdx.x * blockDim.x + threadIdx.x;
    if (idx < E) atomicAdd(&g_CNT[ei[(size_t)E + idx]], 1);
    if (idx < N) atomicAdd(&g_GCNT[batch[idx]], 1);
}

// ---------------- k_gemmPQ: P (K=256) or Q (K=272) ----------------
__global__ void __launch_bounds__(512) k_gemmPQ(const float* __restrict__ B, int K, int outSel, int N) {
    extern __shared__ float sm[];
    float* sA = sm;              // 128*288
    float* sB = sm + 128 * 288;  // 32*256
    int t = threadIdx.x;
    int n0 = blockIdx.x * 128;
    stage_A272(sA, n0, N, t);
    __syncthreads();
    int i = t >> 5, j = t & 31;
    unsigned long long acc[8][4];
#pragma unroll
    for (int r = 0; r < 8; r++)
#pragma unroll
        for (int c = 0; c < 4; c++) acc[r][c] = 0ull;
    int nCh = (K + 31) >> 5;
    for (int ch = 0; ch < nCh; ch++) {
        int k0 = ch * 32;
        stage_B(sB, B, k0, K, t);
        __syncthreads();
        mma_chunk(sA + i * 8 * 288 + k0, 288, sB, j, acc);
        __syncthreads();
    }
    float* OUT = outSel ? g_Q : g_P;
#pragma unroll
    for (int r = 0; r < 8; r++) {
        int n = n0 + i * 8 + r;
        if (n < N) {
            float2 a0 = unpk(acc[r][0]), a1 = unpk(acc[r][1]);
            float2 a2 = unpk(acc[r][2]), a3 = unpk(acc[r][3]);
            *(float4*)(OUT + (size_t)n * Dh + 4 * j)       = make_float4(a0.x, a0.y, a1.x, a1.y);
            *(float4*)(OUT + (size_t)n * Dh + 128 + 4 * j) = make_float4(a2.x, a2.y, a3.x, a3.y);
        }
    }
}

// ---------------- k_msg: build h1 = relu(P[dst]+Q[src]+edge term), GEMM w/ Wm2, scatter ----------------
__global__ void __launch_bounds__(512) k_msg(const float* __restrict__ edge_s, const int* __restrict__ ei,
                                             const float* __restrict__ Wm2, const float* __restrict__ bm2, int E) {
    extern __shared__ float sm[];
    float* h1  = sm;                        // 128*256
    float* sB  = sm + 128 * 256;            // 32*256
    float* sES = sB + 32 * 256;             // 128*17
    int* sSrc  = (int*)(sES + 128 * 17);    // 128
    int* sDst  = sSrc + 128;                // 128
    int t = threadIdx.x;
    int e0 = blockIdx.x * 128;

    if (t < 128)       sSrc[t] = (e0 + t < E) ? ei[e0 + t] : 0;
    else if (t < 256) { int m = t - 128; sDst[m] = (e0 + m < E) ? ei[(size_t)E + e0 + m] : 0; }
    for (int idx = t; idx < 128 * 17; idx += 512) {
        int m = idx / 17, jj = idx - m * 17;
        sES[idx] = (e0 + m < E) ? edge_s[(size_t)(e0 + m) * 17 + jj] : 0.f;
    }
    __syncthreads();
    {
        int k = t & 255, mb = t >> 8;
        float wed[17];
#pragma unroll
        for (int jj = 0; jj < 17; jj++) wed[jj] = g_Wed[jj * 256 + k];
        float bedk = g_bed[k];
        for (int m = mb; m < 128; m += 2) {
            int s_ = sSrc[m], d_ = sDst[m];
            float p = g_P[(size_t)d_ * Dh + k];
            float q = g_Q[(size_t)s_ * Dh + k];
            float r_ = bedk;
#pragma unroll
            for (int jj = 0; jj < 17; jj++) r_ = fmaf(sES[m * 17 + jj], wed[jj], r_);
            h1[m * Dh + k] = fmaxf(p + q + r_, 0.f);
        }
    }
    __syncthreads();
    int i = t >> 5, j = t & 31;
    unsigned long long acc[8][4];
#pragma unroll
    for (int r = 0; r < 8; r++)
#pragma unroll
        for (int c = 0; c < 4; c++) acc[r][c] = 0ull;
    for (int ch = 0; ch < 8; ch++) {
        stage_B(sB, Wm2, ch * 32, 256, t);
        __syncthreads();
        mma_chunk(h1 + i * 8 * Dh + ch * 32, Dh, sB, j, acc);
        __syncthreads();
    }
    float4 b0 = *(const float4*)(bm2 + 4 * j);
    float4 b1 = *(const float4*)(bm2 + 128 + 4 * j);
#pragma unroll
    for (int r = 0; r < 8; r++) {
        int row = i * 8 + r;
        if (e0 + row < E) {
            int d_ = sDst[row];
            float2 a0 = unpk(acc[r][0]), a1 = unpk(acc[r][1]);
            float2 a2 = unpk(acc[r][2]), a3 = unpk(acc[r][3]);
            atomAdd4(g_AGG + (size_t)d_ * Dh + 4 * j,
                     make_float4(a0.x + b0.x, a0.y + b0.y, a1.x + b0.z, a1.y + b0.w));
            atomAdd4(g_AGG + (size_t)d_ * Dh + 128 + 4 * j,
                     make_float4(a2.x + b1.x, a2.y + b1.y, a3.x + b1.z, a3.y + b1.w));
        }
    }
}

// ---------------- k_update: s = s0 + agg / max(cnt,1) ----------------
__global__ void k_update(int N) {
    int idx = blockIdx.x * blockDim.x + threadIdx.x;   // one float4 per thread
    if (idx < N * 64) {
        int n = idx >> 6;
        float inv = 1.f / fmaxf((float)g_CNT[n], 1.f);
        float4 s = *(float4*)(g_S + (size_t)idx * 4);
        float4 a = *(float4*)(g_AGG + (size_t)idx * 4);
        s.x += a.x * inv; s.y += a.y * inv; s.z += a.z * inv; s.w += a.w * inv;
        *(float4*)(g_S + (size_t)idx * 4) = s;
    }
}

// ---------------- k_final: GEMM(Wn) + LayerNorm + ReLU + pooled atomics ----------------
__global__ void __launch_bounds__(512) k_final(const float* __restrict__ Wn, const float* __restrict__ bn,
                                               const float* __restrict__ gamma, const float* __restrict__ beta,
                                               const int* __restrict__ batch, float* __restrict__ out, int N) {
    extern __shared__ float sm[];
    float* sA = sm;
    float* sB = sm + 128 * 288;
    int t = threadIdx.x;
    int n0 = blockIdx.x * 128;
    stage_A272(sA, n0, N, t);
    __syncthreads();
    int i = t >> 5, j = t & 31;
    unsigned long long acc[8][4];
#pragma unroll
    for (int r = 0; r < 8; r++)
#pragma unroll
        for (int c = 0; c < 4; c++) acc[r][c] = 0ull;
    for (int ch = 0; ch < 9; ch++) {
        int k0 = ch * 32;
        stage_B(sB, Wn, k0, 272, t);
        __syncthreads();
        mma_chunk(sA + i * 8 * 288 + k0, 288, sB, j, acc);
        __syncthreads();
    }
    float4 bn0 = *(const float4*)(bn + 4 * j);
    float4 bn1 = *(const float4*)(bn + 128 + 4 * j);
    float4 g0  = *(const float4*)(gamma + 4 * j);
    float4 g1  = *(const float4*)(gamma + 128 + 4 * j);
    float4 be0 = *(const float4*)(beta + 4 * j);
    float4 be1 = *(const float4*)(beta + 128 + 4 * j);
#pragma unroll
    for (int r = 0; r < 8; r++) {
        int n = n0 + i * 8 + r;
        float2 a0 = unpk(acc[r][0]), a1 = unpk(acc[r][1]);
        float2 a2 = unpk(acc[r][2]), a3 = unpk(acc[r][3]);
        float f[8];
        f[0] = a0.x + bn0.x; f[1] = a0.y + bn0.y; f[2] = a1.x + bn0.z; f[3] = a1.y + bn0.w;
        f[4] = a2.x + bn1.x; f[5] = a2.y + bn1.y; f[6] = a3.x + bn1.z; f[7] = a3.y + bn1.w;
        float s = 0.f, sq = 0.f;
#pragma unroll
        for (int c = 0; c < 8; c++) { s += f[c]; sq = fmaf(f[c], f[c], sq); }
#pragma unroll
        for (int off = 16; off > 0; off >>= 1) {
            s  += __shfl_xor_sync(0xFFFFFFFFu, s, off);
            sq += __shfl_xor_sync(0xFFFFFFFFu, sq, off);
        }
        float mu = s * (1.f / 256.f);
        float var = sq * (1.f / 256.f) - mu * mu;
        float rs = rsqrtf(var + 1e-5f);
        float y[8];
        y[0] = fmaxf((f[0] - mu) * rs * g0.x + be0.x, 0.f);
        y[1] = fmaxf((f[1] - mu) * rs * g0.y + be0.y, 0.f);
        y[2] = fmaxf((f[2] - mu) * rs * g0.z + be0.z, 0.f);
        y[3] = fmaxf((f[3] - mu) * rs * g0.w + be0.w, 0.f);
        y[4] = fmaxf((f[4] - mu) * rs * g1.x + be1.x, 0.f);
        y[5] = fmaxf((f[5] - mu) * rs * g1.y + be1.y, 0.f);
        y[6] = fmaxf((f[6] - mu) * rs * g1.z + be1.z, 0.f);
        y[7] = fmaxf((f[7] - mu) * rs * g1.w + be1.w, 0.f);
        if (n < N) {
            int b = batch[n];
            atomAdd4(out + (size_t)b * Dh + 4 * j,       make_float4(y[0], y[1], y[2], y[3]));
            atomAdd4(out + (size_t)b * Dh + 128 + 4 * j, make_float4(y[4], y[5], y[6], y[7]));
        }
    }
}

// ---------------- k_div: out /= max(gcnt,1) ----------------
__global__ void k_div(float* out, int G) {
    int idx = blockIdx.x * blockDim.x + threadIdx.x;
    if (idx < G * Dh) {
        float c = (float)g_GCNT[idx >> 8];
        out[idx] *= 1.f / fmaxf(c, 1.f);
    }
}

// ---------------- launch ----------------
extern "C" void kernel_launch(void* const* d_in, const int* in_sizes, int n_in,
                              void* d_out, int out_size) {
    const float* node_s     = (const float*)d_in[0];
    const float* node_v     = (const float*)d_in[1];
    const float* edge_s     = (const float*)d_in[2];
    const int*   edge_index = (const int*)d_in[3];
    const int*   batch      = (const int*)d_in[4];
    const float* Ws  = (const float*)d_in[5];
    const float* bs  = (const float*)d_in[6];
    const float* Wv  = (const float*)d_in[7];
    const float* bv  = (const float*)d_in[8];
    const float* We  = (const float*)d_in[9];
    const float* be  = (const float*)d_in[10];
    const float* Wm1 = (const float*)d_in[11];
    const float* bm1 = (const float*)d_in[12];
    const float* Wm2 = (const float*)d_in[13];
    const float* bm2 = (const float*)d_in[14];
    const float* Wn  = (const float*)d_in[15];
    const float* bn  = (const float*)d_in[16];
    const float* gamma = (const float*)d_in[17];
    const float* beta  = (const float*)d_in[18];

    int N = in_sizes[0] / 23;
    int E = in_sizes[2] / 17;
    int G = out_size / Dh;
    float* out = (float*)d_out;

    const int SM_GEMM = (128 * 288 + 32 * 256) * 4;                 // 180224 B
    const int SM_MSG  = (128 * 256 + 32 * 256 + 128 * 17) * 4 + 256 * 4;  // 173568 B
    cudaFuncSetAttribute((const void*)k_gemmPQ, cudaFuncAttributeMaxDynamicSharedMemorySize, SM_GEMM);
    cudaFuncSetAttribute((const void*)k_final,  cudaFuncAttributeMaxDynamicSharedMemorySize, SM_GEMM);
    cudaFuncSetAttribute((const void*)k_msg,    cudaFuncAttributeMaxDynamicSharedMemorySize, SM_MSG);

    int mEN = (E > N) ? E : N;

    k_zero<<<1024, 256>>>(out, out_size, N, G);
    k_wed<<<18, 256>>>(We, Wm1, bm1, be);
    k_node<<<(N + 31) / 32, 256>>>(node_s, node_v, Ws, bs, Wv, bv, N);
    k_cnt<<<(mEN + 255) / 256, 256>>>(edge_index, batch, E, N);
    k_gemmPQ<<<(N + 127) / 128, 512, SM_GEMM>>>(Wm1, 256, 0, N);                  // P
    k_gemmPQ<<<(N + 127) / 128, 512, SM_GEMM>>>(Wm1 + 256 * 256, 272, 1, N);      // Q
    k_msg<<<(E + 127) / 128, 512, SM_MSG>>>(edge_s, edge_index, Wm2, bm2, E);
    k_update<<<(N * 64 + 255) / 256, 256>>>(N);
    k_final<<<(N + 127) / 128, 512, SM_GEMM>>>(Wn, bn, gamma, beta, batch, out, N);
    k_div<<<(G * Dh + 255) / 256, 256>>>(out, G);
}

// round 4
// speedup vs baseline: 3.7000x; 3.7000x over previous
#include <cuda_runtime.h>
#include <cstdint>

#define Dh 256
#define NMAX 50048
#define EMAX 400128
#define GMAX 512

// ---------------- scratch (device globals; allocation-free) ----------------
__device__ float g_VN[(size_t)NMAX * 16];      // v_norm
__device__ float g_P[(size_t)NMAX * Dh];       // node_s @ WP            (dst part)
__device__ float g_Q[(size_t)NMAX * Dh];       // node_s @ WQ + vn @ W1c (src part)
__device__ float g_R[(size_t)NMAX * Dh];       // segment_sum(relu(hpre), dst)
__device__ int   g_CNT[NMAX];                  // in-degree per node
__device__ int   g_GCNT[GMAX];                 // nodes per graph
// folded weights
__device__ float g_WPfull[64 * Dh];            // rows 0:23 = Ws@Wm1[0:256], rest 0
__device__ float g_WQfull[64 * Dh];            // rows 0:23 = Ws@Wm1[256:512], 23:39 = Wm1[512:528], rest 0
__device__ float g_WBF[320 * Dh];              // rows 0:256=Wm2@WnS, 256:279=Ws@WnS, 279:295=Wn[256:272], rest 0
__device__ float g_Wed[17 * Dh];               // We[0:17] @ Wm1[528:784]
__device__ float g_bedAll[Dh];                 // bm1 + be@W1d + bs@W1a + bs@W1b
__device__ float g_b0[Dh];                     // bn + bs@WnS
__device__ float g_cB[Dh];                     // bm2@WnS

// ---------------- packed f32x2 helpers ----------------
__device__ __forceinline__ void ffma2(unsigned long long &d, unsigned long long a, unsigned long long b) {
    asm("fma.rn.f32x2 %0, %1, %2, %0;" : "+l"(d) : "l"(a), "l"(b));
}
__device__ __forceinline__ unsigned long long packdup(float a) {
    unsigned long long r;
    asm("mov.b64 %0, {%1, %1};" : "=l"(r) : "f"(a));
    return r;
}
__device__ __forceinline__ float2 unpk(unsigned long long v) {
    float2 f;
    asm("mov.b64 {%0, %1}, %2;" : "=f"(f.x), "=f"(f.y) : "l"(v));
    return f;
}
__device__ __forceinline__ void atomAdd4(float* p, float4 v) {
    asm volatile("red.global.add.v4.f32 [%0], {%1,%2,%3,%4};"
                 :: "l"(p), "f"(v.x), "f"(v.y), "f"(v.z), "f"(v.w) : "memory");
}

// ---------------- GEMM building blocks (BM=128, BN=256, 512 threads) ----------------
// thread t: i = t>>5 -> rows 8i..8i+7 ; j = t&31 -> cols {4j..4j+3, 128+4j..128+4j+3}
// A reads are warp-broadcast (all lanes same addr) -> conflict-free for any lda.
__device__ __forceinline__ void stage_B(float* sB, const float* __restrict__ B, int k0, int t) {
#pragma unroll
    for (int q = 0; q < 4; q++) {
        int idx = t + q * 512;
        int kk = idx >> 6, c4 = idx & 63;
        *(float4*)(sB + kk * Dh + c4 * 4) = *(const float4*)(B + (size_t)(k0 + kk) * Dh + c4 * 4);
    }
}

__device__ __forceinline__ void mma_chunk(const float* aRow, int lda, const float* sB,
                                          int j, unsigned long long acc[8][4]) {
#pragma unroll
    for (int kk = 0; kk < 32; kk += 4) {
        float4 a4[8];
#pragma unroll
        for (int r = 0; r < 8; r++)
            a4[r] = *(const float4*)(aRow + r * lda + kk);
#pragma unroll
        for (int u = 0; u < 4; u++) {
            const float* brow = sB + (kk + u) * Dh + 4 * j;
            ulonglong2 b0 = *(const ulonglong2*)(brow);
            ulonglong2 b1 = *(const ulonglong2*)(brow + 128);
#pragma unroll
            for (int r = 0; r < 8; r++) {
                float av = (u == 0) ? a4[r].x : (u == 1) ? a4[r].y : (u == 2) ? a4[r].z : a4[r].w;
                unsigned long long pa = packdup(av);
                ffma2(acc[r][0], pa, b0.x);
                ffma2(acc[r][1], pa, b0.y);
                ffma2(acc[r][2], pa, b1.x);
                ffma2(acc[r][3], pa, b1.y);
            }
        }
    }
}

// ---------------- k_zero ----------------
__global__ void k_zero(float* out, int outN, int N, int G) {
    size_t stride = (size_t)gridDim.x * blockDim.x;
    size_t idx0 = (size_t)blockIdx.x * blockDim.x + threadIdx.x;
    for (size_t i = idx0; i < (size_t)N * Dh; i += stride) g_R[i] = 0.f;
    for (size_t i = idx0; i < (size_t)N; i += stride) g_CNT[i] = 0;
    for (size_t i = idx0; i < (size_t)G; i += stride) g_GCNT[i] = 0;
    for (size_t i = idx0; i < (size_t)outN; i += stride) out[i] = 0.f;
}

// ---------------- k_prep: all folded weights/biases ----------------
// block b in [0,64): WPfull ; [64,128): WQfull ; [128,448): WBF ; [448,465): Wed ; 465..467: biases
__global__ void k_prep(const float* __restrict__ Ws, const float* __restrict__ bs,
                       const float* __restrict__ We, const float* __restrict__ be,
                       const float* __restrict__ Wm1, const float* __restrict__ bm1,
                       const float* __restrict__ Wm2, const float* __restrict__ bm2,
                       const float* __restrict__ Wn, const float* __restrict__ bn) {
    __shared__ float a[256];
    __shared__ float a2[256];
    int t = threadIdx.x, b = blockIdx.x;
    const float* W1a = Wm1;                         // [256,256]
    const float* W1b = Wm1 + (size_t)256 * 256;
    const float* W1d = Wm1 + (size_t)528 * 256;
    const float* WnS = Wn;                          // [256,256]

    if (b < 64) {                                   // g_WPfull
        int r = b;
        if (r < 23) {
            a[t] = Ws[(size_t)r * 256 + t];
            __syncthreads();
            float acc = 0.f;
            for (int k = 0; k < 256; k++) acc = fmaf(a[k], W1a[(size_t)k * 256 + t], acc);
            g_WPfull[r * 256 + t] = acc;
        } else g_WPfull[r * 256 + t] = 0.f;
    } else if (b < 128) {                           // g_WQfull
        int r = b - 64;
        if (r < 23) {
            a[t] = Ws[(size_t)r * 256 + t];
            __syncthreads();
            float acc = 0.f;
            for (int k = 0; k < 256; k++) acc = fmaf(a[k], W1b[(size_t)k * 256 + t], acc);
            g_WQfull[r * 256 + t] = acc;
        } else if (r < 39) {
            g_WQfull[r * 256 + t] = Wm1[(size_t)(512 + (r - 23)) * 256 + t];
        } else g_WQfull[r * 256 + t] = 0.f;
    } else if (b < 448) {                           // g_WBF
        int r = b - 128;
        if (r < 256) {
            a[t] = Wm2[(size_t)r * 256 + t];
            __syncthreads();
            float acc = 0.f;
            for (int k = 0; k < 256; k++) acc = fmaf(a[k], WnS[(size_t)k * 256 + t], acc);
            g_WBF[r * 256 + t] = acc;
        } else if (r < 279) {
            a[t] = Ws[(size_t)(r - 256) * 256 + t];
            __syncthreads();
            float acc = 0.f;
            for (int k = 0; k < 256; k++) acc = fmaf(a[k], WnS[(size_t)k * 256 + t], acc);
            g_WBF[r * 256 + t] = acc;
        } else if (r < 295) {
            g_WBF[r * 256 + t] = Wn[(size_t)(256 + (r - 279)) * 256 + t];
        } else g_WBF[r * 256 + t] = 0.f;
    } else if (b < 465) {                           // g_Wed
        int r = b - 448;
        a[t] = We[(size_t)r * 256 + t];
        __syncthreads();
        float acc = 0.f;
        for (int k = 0; k < 256; k++) acc = fmaf(a[k], W1d[(size_t)k * 256 + t], acc);
        g_Wed[r * 256 + t] = acc;
    } else if (b == 465) {                          // g_bedAll
        a[t] = bs[t]; a2[t] = be[t];
        __syncthreads();
        float acc = bm1[t];
        for (int k = 0; k < 256; k++) {
            acc = fmaf(a[k], W1a[(size_t)k * 256 + t], acc);
            acc = fmaf(a[k], W1b[(size_t)k * 256 + t], acc);
            acc = fmaf(a2[k], W1d[(size_t)k * 256 + t], acc);
        }
        g_bedAll[t] = acc;
    } else if (b == 466) {                          // g_b0
        a[t] = bs[t];
        __syncthreads();
        float acc = bn[t];
        for (int k = 0; k < 256; k++) acc = fmaf(a[k], WnS[(size_t)k * 256 + t], acc);
        g_b0[t] = acc;
    } else {                                        // g_cB
        a[t] = bm2[t];
        __syncthreads();
        float acc = 0.f;
        for (int k = 0; k < 256; k++) acc = fmaf(a[k], WnS[(size_t)k * 256 + t], acc);
        g_cB[t] = acc;
    }
}

// ---------------- k_vn: vector-channel norms ----------------
__global__ void k_vn(const float* __restrict__ node_v, const float* __restrict__ Wv,
                     const float* __restrict__ bv, int N) {
    __shared__ float sWv[64], sBv[16];
    int t = threadIdx.x;
    if (t < 64) sWv[t] = Wv[t];
    else if (t < 80) sBv[t - 64] = bv[t - 64];
    __syncthreads();
    int idx = blockIdx.x * blockDim.x + t;
    if (idx < N * 16) {
        int n = idx >> 4, o = idx & 15;
        float ss = 0.f;
#pragma unroll
        for (int c = 0; c < 3; c++) {
            float v = sBv[o];
#pragma unroll
            for (int k = 0; k < 4; k++) v = fmaf(node_v[(size_t)n * 12 + k * 3 + c], sWv[k * 16 + o], v);
            ss = fmaf(v, v, ss);
        }
        g_VN[idx] = sqrtf(ss);
    }
}

// ---------------- k_cnt: degree + graph counts ----------------
__global__ void k_cnt(const int* __restrict__ ei, const int* __restrict__ batch, int E, int N) {
    int idx = blockIdx.x * blockDim.x + threadIdx.x;
    if (idx < E) atomicAdd(&g_CNT[ei[(size_t)E + idx]], 1);
    if (idx < N) atomicAdd(&g_GCNT[batch[idx]], 1);
}

// ---------------- k_pq: [node_s|vn|0] (K=64) x {WPfull,WQfull} -> g_P / g_Q ----------------
__global__ void __launch_bounds__(512) k_pq(const float* __restrict__ node_s, int N) {
    extern __shared__ float sm[];
    float* sA = sm;              // 128*64
    float* sB = sm + 128 * 64;   // 32*256
    int t = threadIdx.x;
    int n0 = blockIdx.x * 128;
    const float* B = blockIdx.y ? g_WQfull : g_WPfull;
    float* OUT = blockIdx.y ? g_Q : g_P;

    for (int q = 0; q < 16; q++) {
        int idx = t + q * 512;
        int m = idx >> 6, c = idx & 63;
        int n = n0 + m;
        float v = 0.f;
        if (n < N) {
            if (c < 23) v = node_s[(size_t)n * 23 + c];
            else if (c < 39 && blockIdx.y) v = g_VN[(size_t)n * 16 + (c - 23)];
        }
        sA[m * 64 + c] = v;
    }
    __syncthreads();
    int i = t >> 5, j = t & 31;
    unsigned long long acc[8][4];
#pragma unroll
    for (int r = 0; r < 8; r++)
#pragma unroll
        for (int c = 0; c < 4; c++) acc[r][c] = 0ull;
    for (int ch = 0; ch < 2; ch++) {
        stage_B(sB, B, ch * 32, t);
        __syncthreads();
        mma_chunk(sA + i * 8 * 64 + ch * 32, 64, sB, j, acc);
        __syncthreads();
    }
#pragma unroll
    for (int r = 0; r < 8; r++) {
        int n = n0 + i * 8 + r;
        if (n < N) {
            float2 a0 = unpk(acc[r][0]), a1 = unpk(acc[r][1]);
            float2 a2 = unpk(acc[r][2]), a3 = unpk(acc[r][3]);
            *(float4*)(OUT + (size_t)n * Dh + 4 * j)       = make_float4(a0.x, a0.y, a1.x, a1.y);
            *(float4*)(OUT + (size_t)n * Dh + 128 + 4 * j) = make_float4(a2.x, a2.y, a3.x, a3.y);
        }
    }
}

// ---------------- k_msg: R[dst] += relu(P[dst]+Q[src]+edge_s@Wed+bedAll) ----------------
__global__ void __launch_bounds__(512) k_msg(const float* __restrict__ edge_s,
                                             const int* __restrict__ ei, int E) {
    __shared__ float sES[128 * 17];
    __shared__ int sSrc[128], sDst[128];
    int t = threadIdx.x;
    int e0 = blockIdx.x * 128;
    int kp = t & 127;      // column pair: cols 2kp, 2kp+1
    int mg = t >> 7;       // edge group 0..3 (32 edges each)

    if (t < 128)      sSrc[t] = (e0 + t < E) ? ei[e0 + t] : 0;
    else if (t < 256) { int m = t - 128; sDst[m] = (e0 + m < E) ? ei[(size_t)E + e0 + m] : 0; }
    for (int idx = t; idx < 128 * 17; idx += 512) {
        int m = idx / 17, j = idx - m * 17;
        sES[idx] = (e0 + m < E) ? edge_s[(size_t)(e0 + m) * 17 + j] : 0.f;
    }
    __syncthreads();

    unsigned long long wed2[17];
#pragma unroll
    for (int j = 0; j < 17; j++)
        wed2[j] = *(const unsigned long long*)(g_Wed + j * 256 + 2 * kp);
    unsigned long long bed2 = *(const unsigned long long*)(g_bedAll + 2 * kp);

    bool evenLane = ((kp & 1) == 0);
#pragma unroll 2
    for (int i = 0; i < 32; i++) {
        int m = mg * 32 + i;
        int s_ = sSrc[m], d_ = sDst[m];
        float2 p = *(const float2*)(g_P + (size_t)d_ * Dh + 2 * kp);
        float2 q = *(const float2*)(g_Q + (size_t)s_ * Dh + 2 * kp);
        unsigned long long r2 = bed2;
        const float* es = sES + m * 17;
#pragma unroll
        for (int j = 0; j < 17; j++) ffma2(r2, packdup(es[j]), wed2[j]);
        float2 rr = unpk(r2);
        float h0 = fmaxf(p.x + q.x + rr.x, 0.f);
        float h1 = fmaxf(p.y + q.y + rr.y, 0.f);
        float n0_ = __shfl_down_sync(0xFFFFFFFFu, h0, 1);
        float n1_ = __shfl_down_sync(0xFFFFFFFFu, h1, 1);
        if (evenLane && (e0 + m < E))
            atomAdd4(g_R + (size_t)d_ * Dh + 2 * kp, make_float4(h0, h1, n0_, n1_));
    }
}

// ---------------- k_final: [Rbar|node_s|vn] (K=320) x WBF + bias + LN + ReLU + pool ----------------
__global__ void __launch_bounds__(512) k_final(const float* __restrict__ node_s,
                                               const float* __restrict__ gamma, const float* __restrict__ beta,
                                               const int* __restrict__ batch, float* __restrict__ out, int N) {
    extern __shared__ float sm[];
    float* sA = sm;                 // 128*320
    float* sB = sm + 128 * 320;     // 32*256
    float* sInv = sB + 32 * 256;    // 128
    int t = threadIdx.x;
    int n0 = blockIdx.x * 128;

    if (t < 128) {
        int n = n0 + t;
        sInv[t] = (n < N) ? (1.f / fmaxf((float)g_CNT[n], 1.f)) : 0.f;
    }
    __syncthreads();
    // stage Rbar (cols 0:256) as float4
    for (int q = 0; q < 16; q++) {
        int idx = t + q * 512;                 // 128*64 quads
        int m = idx >> 6, c4 = idx & 63;
        int n = n0 + m;
        float4 v = make_float4(0.f, 0.f, 0.f, 0.f);
        if (n < N) {
            float inv = sInv[m];
            float4 r = *(const float4*)(g_R + (size_t)n * Dh + c4 * 4);
            v = make_float4(r.x * inv, r.y * inv, r.z * inv, r.w * inv);
        }
        *(float4*)(sA + m * 320 + c4 * 4) = v;
    }
    // stage node_s (256:279), vn (279:295), pad (295:320)
    for (int q = 0; q < 16; q++) {
        int idx = t + q * 512;                 // 128*64 scalars
        int m = idx >> 6, c = idx & 63;
        int n = n0 + m;
        float v = 0.f;
        if (n < N) {
            if (c < 23)      v = node_s[(size_t)n * 23 + c];
            else if (c < 39) v = g_VN[(size_t)n * 16 + (c - 23)];
        }
        sA[m * 320 + 256 + c] = v;
    }
    __syncthreads();
    int i = t >> 5, j = t & 31;
    unsigned long long acc[8][4];
#pragma unroll
    for (int r = 0; r < 8; r++)
#pragma unroll
        for (int c = 0; c < 4; c++) acc[r][c] = 0ull;
    for (int ch = 0; ch < 10; ch++) {
        stage_B(sB, g_WBF, ch * 32, t);
        __syncthreads();
        mma_chunk(sA + i * 8 * 320 + ch * 32, 320, sB, j, acc);
        __syncthreads();
    }
    float4 b00 = *(const float4*)(g_b0 + 4 * j);
    float4 b01 = *(const float4*)(g_b0 + 128 + 4 * j);
    float4 cb0 = *(const float4*)(g_cB + 4 * j);
    float4 cb1 = *(const float4*)(g_cB + 128 + 4 * j);
    float4 g0  = *(const float4*)(gamma + 4 * j);
    float4 g1  = *(const float4*)(gamma + 128 + 4 * j);
    float4 be0 = *(const float4*)(beta + 4 * j);
    float4 be1 = *(const float4*)(beta + 128 + 4 * j);
#pragma unroll
    for (int r = 0; r < 8; r++) {
        int n = n0 + i * 8 + r;
        float chi = 0.f;
        if (n < N) chi = (g_CNT[n] > 0) ? 1.f : 0.f;
        float2 a0 = unpk(acc[r][0]), a1 = unpk(acc[r][1]);
        float2 a2 = unpk(acc[r][2]), a3 = unpk(acc[r][3]);
        float f[8];
        f[0] = a0.x + b00.x + chi * cb0.x; f[1] = a0.y + b00.y + chi * cb0.y;
        f[2] = a1.x + b00.z + chi * cb0.z; f[3] = a1.y + b00.w + chi * cb0.w;
        f[4] = a2.x + b01.x + chi * cb1.x; f[5] = a2.y + b01.y + chi * cb1.y;
        f[6] = a3.x + b01.z + chi * cb1.z; f[7] = a3.y + b01.w + chi * cb1.w;
        float s = 0.f, sq = 0.f;
#pragma unroll
        for (int c = 0; c < 8; c++) { s += f[c]; sq = fmaf(f[c], f[c], sq); }
#pragma unroll
        for (int off = 16; off > 0; off >>= 1) {
            s  += __shfl_xor_sync(0xFFFFFFFFu, s, off);
            sq += __shfl_xor_sync(0xFFFFFFFFu, sq, off);
        }
        float mu = s * (1.f / 256.f);
        float var = sq * (1.f / 256.f) - mu * mu;
        float rs = rsqrtf(var + 1e-5f);
        float y[8];
        y[0] = fmaxf((f[0] - mu) * rs * g0.x + be0.x, 0.f);
        y[1] = fmaxf((f[1] - mu) * rs * g0.y + be0.y, 0.f);
        y[2] = fmaxf((f[2] - mu) * rs * g0.z + be0.z, 0.f);
        y[3] = fmaxf((f[3] - mu) * rs * g0.w + be0.w, 0.f);
        y[4] = fmaxf((f[4] - mu) * rs * g1.x + be1.x, 0.f);
        y[5] = fmaxf((f[5] - mu) * rs * g1.y + be1.y, 0.f);
        y[6] = fmaxf((f[6] - mu) * rs * g1.z + be1.z, 0.f);
        y[7] = fmaxf((f[7] - mu) * rs * g1.w + be1.w, 0.f);
        if (n < N) {
            int b = batch[n];
            atomAdd4(out + (size_t)b * Dh + 4 * j,       make_float4(y[0], y[1], y[2], y[3]));
            atomAdd4(out + (size_t)b * Dh + 128 + 4 * j, make_float4(y[4], y[5], y[6], y[7]));
        }
    }
}

// ---------------- k_div: out /= max(gcnt,1) ----------------
__global__ void k_div(float* out, int G) {
    int idx = blockIdx.x * blockDim.x + threadIdx.x;
    if (idx < G * Dh) {
        float c = (float)g_GCNT[idx >> 8];
        out[idx] *= 1.f / fmaxf(c, 1.f);
    }
}

// ---------------- launch ----------------
extern "C" void kernel_launch(void* const* d_in, const int* in_sizes, int n_in,
                              void* d_out, int out_size) {
    const float* node_s     = (const float*)d_in[0];
    const float* node_v     = (const float*)d_in[1];
    const float* edge_s     = (const float*)d_in[2];
    const int*   edge_index = (const int*)d_in[3];
    const int*   batch      = (const int*)d_in[4];
    const float* Ws  = (const float*)d_in[5];
    const float* bs  = (const float*)d_in[6];
    const float* Wv  = (const float*)d_in[7];
    const float* bv  = (const float*)d_in[8];
    const float* We  = (const float*)d_in[9];
    const float* be  = (const float*)d_in[10];
    const float* Wm1 = (const float*)d_in[11];
    const float* bm1 = (const float*)d_in[12];
    const float* Wm2 = (const float*)d_in[13];
    const float* bm2 = (const float*)d_in[14];
    const float* Wn  = (const float*)d_in[15];
    const float* bn  = (const float*)d_in[16];
    const float* gamma = (const float*)d_in[17];
    const float* beta  = (const float*)d_in[18];

    int N = in_sizes[0] / 23;
    int E = in_sizes[2] / 17;
    int G = out_size / Dh;
    float* out = (float*)d_out;

    const int SM_PQ    = (128 * 64 + 32 * 256) * 4;            // 65536
    const int SM_FINAL = (128 * 320 + 32 * 256 + 128) * 4;     // 197120
    cudaFuncSetAttribute((const void*)k_pq,    cudaFuncAttributeMaxDynamicSharedMemorySize, SM_PQ);
    cudaFuncSetAttribute((const void*)k_final, cudaFuncAttributeMaxDynamicSharedMemorySize, SM_FINAL);

    int mEN = (E > N) ? E : N;

    k_zero<<<1024, 256>>>(out, out_size, N, G);
    k_prep<<<468, 256>>>(Ws, bs, We, be, Wm1, bm1, Wm2, bm2, Wn, bn);
    k_vn<<<(N * 16 + 255) / 256, 256>>>(node_v, Wv, bv, N);
    k_cnt<<<(mEN + 255) / 256, 256>>>(edge_index, batch, E, N);
    dim3 gpq((N + 127) / 128, 2);
    k_pq<<<gpq, 512, SM_PQ>>>(node_s, N);
    k_msg<<<(E + 127) / 128, 512>>>(edge_s, edge_index, E);
    k_final<<<(N + 127) / 128, 512, SM_FINAL>>>(node_s, gamma, beta, batch, out, N);
    k_div<<<(G * Dh + 255) / 256, 256>>>(out, G);
}

// round 5
// speedup vs baseline: 3.7982x; 1.0265x over previous
#include <cuda_runtime.h>
#include <cstdint>

#define Dh 256
#define NMAX 50048
#define EMAX 400128
#define GMAX 512
#define MB 16   // dst-nodes per k_msgs block

typedef unsigned long long ull;

// ---------------- scratch (device globals; allocation-free) ----------------
__device__ float g_VN[(size_t)NMAX * 16];      // v_norm
__device__ float g_P[(size_t)NMAX * Dh];       // node_s @ WP            (dst part)
__device__ float g_Q[(size_t)NMAX * Dh];       // node_s @ WQ + vn @ W1c (src part)
__device__ float g_R[(size_t)NMAX * Dh];       // segment_sum(relu(hpre), dst) -- plain stores
__device__ int   g_CNT[NMAX];                  // in-degree per node
__device__ int   g_GCNT[GMAX];                 // nodes per graph
__device__ int   g_OFF[NMAX + 1];              // exclusive prefix of CNT
__device__ int   g_POS[NMAX];                  // scatter cursor
__device__ int   g_ESRC[EMAX];                 // src of dst-sorted edges
__device__ int   g_EIDX[EMAX];                 // original edge id of sorted edges
// folded weights
__device__ float g_WPfull[64 * Dh];            // rows 0:23 = Ws@Wm1[0:256]
__device__ float g_WQfull[64 * Dh];            // rows 0:23 = Ws@Wm1[256:512], 23:39 = Wm1[512:528]
__device__ float g_WBF[320 * Dh];              // 0:256=Wm2@WnS, 256:279=Ws@WnS, 279:295=Wn[256:272]
__device__ float g_Wed[17 * Dh];               // We[0:17] @ Wm1[528:784]
__device__ float g_bedAll[Dh];                 // bm1 + be@W1d + bs@W1a + bs@W1b
__device__ float g_b0[Dh];                     // bn + bs@WnS
__device__ float g_cB[Dh];                     // bm2@WnS

// ---------------- packed f32x2 helpers ----------------
__device__ __forceinline__ void ffma2(ull &d, ull a, ull b) {
    asm("fma.rn.f32x2 %0, %1, %2, %0;" : "+l"(d) : "l"(a), "l"(b));
}
__device__ __forceinline__ ull packdup(float a) {
    ull r;
    asm("mov.b64 %0, {%1, %1};" : "=l"(r) : "f"(a));
    return r;
}
__device__ __forceinline__ float2 unpk(ull v) {
    float2 f;
    asm("mov.b64 {%0, %1}, %2;" : "=f"(f.x), "=f"(f.y) : "l"(v));
    return f;
}
__device__ __forceinline__ void atomAdd4(float* p, float4 v) {
    asm volatile("red.global.add.v4.f32 [%0], {%1,%2,%3,%4};"
                 :: "l"(p), "f"(v.x), "f"(v.y), "f"(v.z), "f"(v.w) : "memory");
}

// ---------------- GEMM building blocks (BM=128, BN=256, 512 threads) ----------------
__device__ __forceinline__ void stage_B(float* sB, const float* __restrict__ B, int k0, int t) {
#pragma unroll
    for (int q = 0; q < 4; q++) {
        int idx = t + q * 512;
        int kk = idx >> 6, c4 = idx & 63;
        *(float4*)(sB + kk * Dh + c4 * 4) = *(const float4*)(B + (size_t)(k0 + kk) * Dh + c4 * 4);
    }
}

__device__ __forceinline__ void mma_chunk(const float* aRow, int lda, const float* sB,
                                          int j, ull acc[8][4]) {
#pragma unroll
    for (int kk = 0; kk < 32; kk += 4) {
        float4 a4[8];
#pragma unroll
        for (int r = 0; r < 8; r++)
            a4[r] = *(const float4*)(aRow + r * lda + kk);
#pragma unroll
        for (int u = 0; u < 4; u++) {
            const float* brow = sB + (kk + u) * Dh + 4 * j;
            ulonglong2 b0 = *(const ulonglong2*)(brow);
            ulonglong2 b1 = *(const ulonglong2*)(brow + 128);
#pragma unroll
            for (int r = 0; r < 8; r++) {
                float av = (u == 0) ? a4[r].x : (u == 1) ? a4[r].y : (u == 2) ? a4[r].z : a4[r].w;
                ull pa = packdup(av);
                ffma2(acc[r][0], pa, b0.x);
                ffma2(acc[r][1], pa, b0.y);
                ffma2(acc[r][2], pa, b1.x);
                ffma2(acc[r][3], pa, b1.y);
            }
        }
    }
}

// ---------------- k_zero: out + counters only (g_R no longer needs zeroing) ----------------
__global__ void k_zero(float* out, int outN, int N, int G) {
    int stride = gridDim.x * blockDim.x;
    int idx0 = blockIdx.x * blockDim.x + threadIdx.x;
    for (int i = idx0; i < outN; i += stride) out[i] = 0.f;
    for (int i = idx0; i < N; i += stride) g_CNT[i] = 0;
    for (int i = idx0; i < G; i += stride) g_GCNT[i] = 0;
}

// ---------------- k_prep: all folded weights/biases ----------------
__global__ void k_prep(const float* __restrict__ Ws, const float* __restrict__ bs,
                       const float* __restrict__ We, const float* __restrict__ be,
                       const float* __restrict__ Wm1, const float* __restrict__ bm1,
                       const float* __restrict__ Wm2, const float* __restrict__ bm2,
                       const float* __restrict__ Wn, const float* __restrict__ bn) {
    __shared__ float a[256];
    __shared__ float a2[256];
    int t = threadIdx.x, b = blockIdx.x;
    const float* W1a = Wm1;
    const float* W1b = Wm1 + (size_t)256 * 256;
    const float* W1d = Wm1 + (size_t)528 * 256;
    const float* WnS = Wn;

    if (b < 64) {
        int r = b;
        if (r < 23) {
            a[t] = Ws[(size_t)r * 256 + t];
            __syncthreads();
            float acc = 0.f;
            for (int k = 0; k < 256; k++) acc = fmaf(a[k], W1a[(size_t)k * 256 + t], acc);
            g_WPfull[r * 256 + t] = acc;
        } else g_WPfull[r * 256 + t] = 0.f;
    } else if (b < 128) {
        int r = b - 64;
        if (r < 23) {
            a[t] = Ws[(size_t)r * 256 + t];
            __syncthreads();
            float acc = 0.f;
            for (int k = 0; k < 256; k++) acc = fmaf(a[k], W1b[(size_t)k * 256 + t], acc);
            g_WQfull[r * 256 + t] = acc;
        } else if (r < 39) {
            g_WQfull[r * 256 + t] = Wm1[(size_t)(512 + (r - 23)) * 256 + t];
        } else g_WQfull[r * 256 + t] = 0.f;
    } else if (b < 448) {
        int r = b - 128;
        if (r < 256) {
            a[t] = Wm2[(size_t)r * 256 + t];
            __syncthreads();
            float acc = 0.f;
            for (int k = 0; k < 256; k++) acc = fmaf(a[k], WnS[(size_t)k * 256 + t], acc);
            g_WBF[r * 256 + t] = acc;
        } else if (r < 279) {
            a[t] = Ws[(size_t)(r - 256) * 256 + t];
            __syncthreads();
            float acc = 0.f;
            for (int k = 0; k < 256; k++) acc = fmaf(a[k], WnS[(size_t)k * 256 + t], acc);
            g_WBF[r * 256 + t] = acc;
        } else if (r < 295) {
            g_WBF[r * 256 + t] = Wn[(size_t)(256 + (r - 279)) * 256 + t];
        } else g_WBF[r * 256 + t] = 0.f;
    } else if (b < 465) {
        int r = b - 448;
        a[t] = We[(size_t)r * 256 + t];
        __syncthreads();
        float acc = 0.f;
        for (int k = 0; k < 256; k++) acc = fmaf(a[k], W1d[(size_t)k * 256 + t], acc);
        g_Wed[r * 256 + t] = acc;
    } else if (b == 465) {
        a[t] = bs[t]; a2[t] = be[t];
        __syncthreads();
        float acc = bm1[t];
        for (int k = 0; k < 256; k++) {
            acc = fmaf(a[k], W1a[(size_t)k * 256 + t], acc);
            acc = fmaf(a[k], W1b[(size_t)k * 256 + t], acc);
            acc = fmaf(a2[k], W1d[(size_t)k * 256 + t], acc);
        }
        g_bedAll[t] = acc;
    } else if (b == 466) {
        a[t] = bs[t];
        __syncthreads();
        float acc = bn[t];
        for (int k = 0; k < 256; k++) acc = fmaf(a[k], WnS[(size_t)k * 256 + t], acc);
        g_b0[t] = acc;
    } else {
        a[t] = bm2[t];
        __syncthreads();
        float acc = 0.f;
        for (int k = 0; k < 256; k++) acc = fmaf(a[k], WnS[(size_t)k * 256 + t], acc);
        g_cB[t] = acc;
    }
}

// ---------------- k_vn ----------------
__global__ void k_vn(const float* __restrict__ node_v, const float* __restrict__ Wv,
                     const float* __restrict__ bv, int N) {
    __shared__ float sWv[64], sBv[16];
    int t = threadIdx.x;
    if (t < 64) sWv[t] = Wv[t];
    else if (t < 80) sBv[t - 64] = bv[t - 64];
    __syncthreads();
    int idx = blockIdx.x * blockDim.x + t;
    if (idx < N * 16) {
        int n = idx >> 4, o = idx & 15;
        float ss = 0.f;
#pragma unroll
        for (int c = 0; c < 3; c++) {
            float v = sBv[o];
#pragma unroll
            for (int k = 0; k < 4; k++) v = fmaf(node_v[(size_t)n * 12 + k * 3 + c], sWv[k * 16 + o], v);
            ss = fmaf(v, v, ss);
        }
        g_VN[idx] = sqrtf(ss);
    }
}

// ---------------- k_cnt ----------------
__global__ void k_cnt(const int* __restrict__ ei, const int* __restrict__ batch, int E, int N) {
    int idx = blockIdx.x * blockDim.x + threadIdx.x;
    if (idx < E) atomicAdd(&g_CNT[ei[(size_t)E + idx]], 1);
    if (idx < N) atomicAdd(&g_GCNT[batch[idx]], 1);
}

// ---------------- k_scan: exclusive prefix over g_CNT (single block) ----------------
__global__ void __launch_bounds__(1024) k_scan(int N) {
    __shared__ int part[1024];
    int t = threadIdx.x;
    int chunk = (N + 1023) >> 10;
    int beg = t * chunk, end = beg + chunk;
    if (end > N) end = N;
    int s = 0;
    for (int i = beg; i < end; i++) s += g_CNT[i];
    part[t] = s;
    __syncthreads();
    for (int off = 1; off < 1024; off <<= 1) {
        int v = (t >= off) ? part[t - off] : 0;
        __syncthreads();
        part[t] += v;
        __syncthreads();
    }
    int base = (t == 0) ? 0 : part[t - 1];
    for (int i = beg; i < end; i++) {
        g_OFF[i] = base;
        g_POS[i] = base;
        base += g_CNT[i];
    }
    if (t == 1023) g_OFF[N] = part[1023];
}

// ---------------- k_scatter: counting-sort edges by dst ----------------
__global__ void k_scatter(const int* __restrict__ ei, int E) {
    int e = blockIdx.x * blockDim.x + threadIdx.x;
    if (e < E) {
        int d = ei[(size_t)E + e];
        int pos = atomicAdd(&g_POS[d], 1);
        g_ESRC[pos] = ei[e];
        g_EIDX[pos] = e;
    }
}

// ---------------- k_pq: [node_s(|vn)] x {WPfull(K=32), WQfull(K=64)} -> g_P / g_Q ----------------
__global__ void __launch_bounds__(512) k_pq(const float* __restrict__ node_s, int N) {
    extern __shared__ float sm[];
    float* sA = sm;              // up to 128*64
    float* sB = sm + 128 * 64;   // 32*256
    int t = threadIdx.x;
    int n0 = blockIdx.x * 128;
    int isQ = blockIdx.y;
    const float* B = isQ ? g_WQfull : g_WPfull;
    float* OUT = isQ ? g_Q : g_P;
    int KC = isQ ? 64 : 32;

    if (isQ) {
        for (int q = 0; q < 16; q++) {
            int idx = t + q * 512;
            int m = idx >> 6, c = idx & 63;
            int n = n0 + m;
            float v = 0.f;
            if (n < N) {
                if (c < 23) v = node_s[(size_t)n * 23 + c];
                else if (c < 39) v = g_VN[(size_t)n * 16 + (c - 23)];
            }
            sA[m * 64 + c] = v;
        }
    } else {
        for (int q = 0; q < 8; q++) {
            int idx = t + q * 512;
            int m = idx >> 5, c = idx & 31;
            int n = n0 + m;
            float v = 0.f;
            if (n < N && c < 23) v = node_s[(size_t)n * 23 + c];
            sA[m * 32 + c] = v;
        }
    }
    __syncthreads();
    int i = t >> 5, j = t & 31;
    ull acc[8][4];
#pragma unroll
    for (int r = 0; r < 8; r++)
#pragma unroll
        for (int c = 0; c < 4; c++) acc[r][c] = 0ull;
    int nCh = KC >> 5;
    for (int ch = 0; ch < nCh; ch++) {
        stage_B(sB, B, ch * 32, t);
        __syncthreads();
        mma_chunk(sA + i * 8 * KC + ch * 32, KC, sB, j, acc);
        __syncthreads();
    }
#pragma unroll
    for (int r = 0; r < 8; r++) {
        int n = n0 + i * 8 + r;
        if (n < N) {
            float2 a0 = unpk(acc[r][0]), a1 = unpk(acc[r][1]);
            float2 a2 = unpk(acc[r][2]), a3 = unpk(acc[r][3]);
            *(float4*)(OUT + (size_t)n * Dh + 4 * j)       = make_float4(a0.x, a0.y, a1.x, a1.y);
            *(float4*)(OUT + (size_t)n * Dh + 128 + 4 * j) = make_float4(a2.x, a2.y, a3.x, a3.y);
        }
    }
}

// ---------------- k_msgs: atomic-free sorted message accumulation ----------------
// block = 128 threads (one col-pair each), MB=16 dst nodes, edges [OFF[n0], OFF[n0+MB])
__global__ void __launch_bounds__(128) k_msgs(const float* __restrict__ edge_s, int N) {
    __shared__ ull  sES[128 * 17];     // duplicated-pair edge features
    __shared__ int  sSrc[128];
    __shared__ unsigned char sNd[128];
    __shared__ int  sOff[MB + 1];
    int t = threadIdx.x;
    int n0 = blockIdx.x * MB;
    int nCnt = N - n0; if (nCnt > MB) nCnt = MB;
    if (t <= nCnt) sOff[t] = g_OFF[n0 + t];
    __syncthreads();
    int eBeg = sOff[0], eEnd = sOff[nCnt];
    if (eBeg == eEnd) return;

    ull wed2[17];
#pragma unroll
    for (int j = 0; j < 17; j++)
        wed2[j] = *(const ull*)(g_Wed + j * 256 + 2 * t);
    ull bed2 = *(const ull*)(g_bedAll + 2 * t);

    int cur = -1;
    float2 acc = make_float2(0.f, 0.f);
    float2 pcur = make_float2(0.f, 0.f);

    for (int cBase = eBeg; cBase < eEnd; cBase += 128) {
        int len = eEnd - cBase; if (len > 128) len = 128;
        __syncthreads();
        for (int idx = t; idx < len * 17; idx += 128) {
            int m = idx / 17, j = idx - m * 17;
            sES[idx] = packdup(edge_s[(size_t)g_EIDX[cBase + m] * 17 + j]);
        }
        if (t < len) {
            sSrc[t] = g_ESRC[cBase + t];
            int pos = cBase + t;
            int lo = 0, hi = nCnt - 1;
            while (lo < hi) {
                int mid = (lo + hi) >> 1;
                if (pos >= sOff[mid + 1]) lo = mid + 1; else hi = mid;
            }
            sNd[t] = (unsigned char)lo;
        }
        __syncthreads();
        for (int m = 0; m < len; m++) {
            int nd = sNd[m];
            if (nd != cur) {
                if (cur >= 0)
                    *(float2*)(g_R + (size_t)(n0 + cur) * Dh + 2 * t) = acc;
                cur = nd;
                pcur = *(const float2*)(g_P + (size_t)(n0 + nd) * Dh + 2 * t);
                acc = make_float2(0.f, 0.f);
            }
            int s_ = sSrc[m];
            float2 q = *(const float2*)(g_Q + (size_t)s_ * Dh + 2 * t);
            ull r2 = bed2;
            const ull* es = sES + m * 17;
#pragma unroll
            for (int j = 0; j < 17; j++) ffma2(r2, es[j], wed2[j]);
            float2 rr = unpk(r2);
            acc.x += fmaxf(pcur.x + q.x + rr.x, 0.f);
            acc.y += fmaxf(pcur.y + q.y + rr.y, 0.f);
        }
    }
    if (cur >= 0)
        *(float2*)(g_R + (size_t)(n0 + cur) * Dh + 2 * t) = acc;
}

// ---------------- k_final: [Rbar|node_s|vn] (K=320) x WBF + bias + LN + ReLU + pool ----------------
__global__ void __launch_bounds__(512) k_final(const float* __restrict__ node_s,
                                               const float* __restrict__ gamma, const float* __restrict__ beta,
                                               const int* __restrict__ batch, float* __restrict__ out, int N) {
    extern __shared__ float sm[];
    float* sA = sm;                 // 128*320
    float* sB = sm + 128 * 320;     // 32*256
    float* sInv = sB + 32 * 256;    // 128 (0 when cnt==0 -> masks stale R)
    float* sChi = sInv + 128;       // 128
    int t = threadIdx.x;
    int n0 = blockIdx.x * 128;

    if (t < 128) {
        int n = n0 + t;
        int c = (n < N) ? g_CNT[n] : 0;
        sInv[t] = (c > 0) ? (1.f / (float)c) : 0.f;
        sChi[t] = (c > 0) ? 1.f : 0.f;
    }
    __syncthreads();
    for (int q = 0; q < 16; q++) {
        int idx = t + q * 512;
        int m = idx >> 6, c4 = idx & 63;
        int n = n0 + m;
        float4 v = make_float4(0.f, 0.f, 0.f, 0.f);
        if (n < N) {
            float inv = sInv[m];
            if (inv != 0.f) {
                float4 r = *(const float4*)(g_R + (size_t)n * Dh + c4 * 4);
                v = make_float4(r.x * inv, r.y * inv, r.z * inv, r.w * inv);
            }
        }
        *(float4*)(sA + m * 320 + c4 * 4) = v;
    }
    for (int q = 0; q < 16; q++) {
        int idx = t + q * 512;
        int m = idx >> 6, c = idx & 63;
        int n = n0 + m;
        float v = 0.f;
        if (n < N) {
            if (c < 23)      v = node_s[(size_t)n * 23 + c];
            else if (c < 39) v = g_VN[(size_t)n * 16 + (c - 23)];
        }
        sA[m * 320 + 256 + c] = v;
    }
    __syncthreads();
    int i = t >> 5, j = t & 31;
    ull acc[8][4];
#pragma unroll
    for (int r = 0; r < 8; r++)
#pragma unroll
        for (int c = 0; c < 4; c++) acc[r][c] = 0ull;
    for (int ch = 0; ch < 10; ch++) {
        stage_B(sB, g_WBF, ch * 32, t);
        __syncthreads();
        mma_chunk(sA + i * 8 * 320 + ch * 32, 320, sB, j, acc);
        __syncthreads();
    }
    float4 b00 = *(const float4*)(g_b0 + 4 * j);
    float4 b01 = *(const float4*)(g_b0 + 128 + 4 * j);
    float4 cb0 = *(const float4*)(g_cB + 4 * j);
    float4 cb1 = *(const float4*)(g_cB + 128 + 4 * j);
    float4 g0  = *(const float4*)(gamma + 4 * j);
    float4 g1  = *(const float4*)(gamma + 128 + 4 * j);
    float4 be0 = *(const float4*)(beta + 4 * j);
    float4 be1 = *(const float4*)(beta + 128 + 4 * j);
#pragma unroll
    for (int r = 0; r < 8; r++) {
        int n = n0 + i * 8 + r;
        float chi = sChi[i * 8 + r];
        float2 a0 = unpk(acc[r][0]), a1 = unpk(acc[r][1]);
        float2 a2 = unpk(acc[r][2]), a3 = unpk(acc[r][3]);
        float f[8];
        f[0] = a0.x + b00.x + chi * cb0.x; f[1] = a0.y + b00.y + chi * cb0.y;
        f[2] = a1.x + b00.z + chi * cb0.z; f[3] = a1.y + b00.w + chi * cb0.w;
        f[4] = a2.x + b01.x + chi * cb1.x; f[5] = a2.y + b01.y + chi * cb1.y;
        f[6] = a3.x + b01.z + chi * cb1.z; f[7] = a3.y + b01.w + chi * cb1.w;
        float s = 0.f, sq = 0.f;
#pragma unroll
        for (int c = 0; c < 8; c++) { s += f[c]; sq = fmaf(f[c], f[c], sq); }
#pragma unroll
        for (int off = 16; off > 0; off >>= 1) {
            s  += __shfl_xor_sync(0xFFFFFFFFu, s, off);
            sq += __shfl_xor_sync(0xFFFFFFFFu, sq, off);
        }
        float mu = s * (1.f / 256.f);
        float var = sq * (1.f / 256.f) - mu * mu;
        float rs = rsqrtf(var + 1e-5f);
        float y[8];
        y[0] = fmaxf((f[0] - mu) * rs * g0.x + be0.x, 0.f);
        y[1] = fmaxf((f[1] - mu) * rs * g0.y + be0.y, 0.f);
        y[2] = fmaxf((f[2] - mu) * rs * g0.z + be0.z, 0.f);
        y[3] = fmaxf((f[3] - mu) * rs * g0.w + be0.w, 0.f);
        y[4] = fmaxf((f[4] - mu) * rs * g1.x + be1.x, 0.f);
        y[5] = fmaxf((f[5] - mu) * rs * g1.y + be1.y, 0.f);
        y[6] = fmaxf((f[6] - mu) * rs * g1.z + be1.z, 0.f);
        y[7] = fmaxf((f[7] - mu) * rs * g1.w + be1.w, 0.f);
        if (n < N) {
            int b = batch[n];
            atomAdd4(out + (size_t)b * Dh + 4 * j,       make_float4(y[0], y[1], y[2], y[3]));
            atomAdd4(out + (size_t)b * Dh + 128 + 4 * j, make_float4(y[4], y[5], y[6], y[7]));
        }
    }
}

// ---------------- k_div ----------------
__global__ void k_div(float* out, int G) {
    int idx = blockIdx.x * blockDim.x + threadIdx.x;
    if (idx < G * Dh) {
        float c = (float)g_GCNT[idx >> 8];
        out[idx] *= 1.f / fmaxf(c, 1.f);
    }
}

// ---------------- launch ----------------
extern "C" void kernel_launch(void* const* d_in, const int* in_sizes, int n_in,
                              void* d_out, int out_size) {
    const float* node_s     = (const float*)d_in[0];
    const float* node_v     = (const float*)d_in[1];
    const float* edge_s     = (const float*)d_in[2];
    const int*   edge_index = (const int*)d_in[3];
    const int*   batch      = (const int*)d_in[4];
    const float* Ws  = (const float*)d_in[5];
    const float* bs  = (const float*)d_in[6];
    const float* Wv  = (const float*)d_in[7];
    const float* bv  = (const float*)d_in[8];
    const float* We  = (const float*)d_in[9];
    const float* be  = (const float*)d_in[10];
    const float* Wm1 = (const float*)d_in[11];
    const float* bm1 = (const float*)d_in[12];
    const float* Wm2 = (const float*)d_in[13];
    const float* bm2 = (const float*)d_in[14];
    const float* Wn  = (const float*)d_in[15];
    const float* bn  = (const float*)d_in[16];
    const float* gamma = (const float*)d_in[17];
    const float* beta  = (const float*)d_in[18];

    int N = in_sizes[0] / 23;
    int E = in_sizes[2] / 17;
    int G = out_size / Dh;
    float* out = (float*)d_out;

    const int SM_PQ    = (128 * 64 + 32 * 256) * 4;                  // 65536
    const int SM_FINAL = (128 * 320 + 32 * 256 + 256) * 4;           // 197632
    cudaFuncSetAttribute((const void*)k_pq,    cudaFuncAttributeMaxDynamicSharedMemorySize, SM_PQ);
    cudaFuncSetAttribute((const void*)k_final, cudaFuncAttributeMaxDynamicSharedMemorySize, SM_FINAL);

    int mEN = (E > N) ? E : N;

    k_zero<<<456, 256>>>(out, out_size, N, G);
    k_prep<<<468, 256>>>(Ws, bs, We, be, Wm1, bm1, Wm2, bm2, Wn, bn);
    k_vn<<<(N * 16 + 255) / 256, 256>>>(node_v, Wv, bv, N);
    k_cnt<<<(mEN + 255) / 256, 256>>>(edge_index, batch, E, N);
    k_scan<<<1, 1024>>>(N);
    k_scatter<<<(E + 255) / 256, 256>>>(edge_index, E);
    dim3 gpq((N + 127) / 128, 2);
    k_pq<<<gpq, 512, SM_PQ>>>(node_s, N);
    k_msgs<<<(N + MB - 1) / MB, 128>>>(edge_s, N);
    k_final<<<(N + 127) / 128, 512, SM_FINAL>>>(node_s, gamma, beta, batch, out, N);
    k_div<<<(G * Dh + 255) / 256, 256>>>(out, G);
}